// round 7
// baseline (speedup 1.0000x reference)
#include <cuda_runtime.h>
#include <math.h>
#include <cstdint>

#define BATCH 32
#define SEQ   256
#define HID   768

#define NTP 512                 // 16 warps = 4 (m) x 4 (n)
#define KC  128                 // s8 elems per K chunk (128B rows)
#define NCH 6                   // K chunks per n-half (768/128)
#define ROWB 144                // 128B data + 16B pad (4r % 32 banks, distinct)

// tile buffer layout (per stage)
#define OFF_AH 0
#define OFF_AL 18432
#define OFF_BH 36864
#define OFF_BL 55296
#define BUFSZ  73728

// smem offsets
#define SM_WD   0
#define SM_KV   1024
#define SM_KS   2048
#define SM_QS   3072
#define SM_RED  3584
#define SM_HM   3648
#define SM_HZ   4160
#define SM_HS   4672
#define SM_SMAX 5184
#define SM_SZ   7232
#define SM_SS   9280
#define SM_TILES 11392
#define SMEM_TOTAL (SM_TILES + 2 * BUFSZ)   // 158848

#define NEG_HUGE (-3.402823466e38f)

// Scratch (allocation-free rule: __device__ globals)
__device__ int8_t g_qh8[BATCH * SEQ * HID];
__device__ int8_t g_ql8[BATCH * SEQ * HID];
__device__ int8_t g_kh8[BATCH * SEQ * HID];
__device__ int8_t g_kl8[BATCH * SEQ * HID];
__device__ float  g_qs[BATCH * SEQ];
__device__ float  g_ks[BATCH * SEQ];
__device__ float  g_wd[SEQ];
__device__ float  g_invden[BATCH];
__device__ float  g_partial[BATCH * BATCH * 2];

__device__ __forceinline__ uint32_t smem_u32(const void* p) {
    uint32_t a;
    asm("{ .reg .u64 t; cvta.to.shared.u64 t, %1; cvt.u32.u64 %0, t; }" : "=r"(a) : "l"(p));
    return a;
}

#define LDSM4(A, addr)                                                          \
    asm volatile("ldmatrix.sync.aligned.m8n8.x4.shared.b16 {%0,%1,%2,%3}, [%4];"\
        : "=r"((A)[0]), "=r"((A)[1]), "=r"((A)[2]), "=r"((A)[3]) : "r"(addr))

#define IMMA(acc, A, b0, b1)                                                    \
    asm volatile("mma.sync.aligned.m16n8k32.row.col.s32.s8.s8.s32 "             \
        "{%0,%1,%2,%3}, {%4,%5,%6,%7}, {%8,%9}, {%0,%1,%2,%3};"                 \
        : "+r"((acc)[0]), "+r"((acc)[1]), "+r"((acc)[2]), "+r"((acc)[3])        \
        : "r"((A)[0]), "r"((A)[1]), "r"((A)[2]), "r"((A)[3]), "r"(b0), "r"(b1))

#define CP16(d, s) \
    asm volatile("cp.async.cg.shared.global [%0], [%1], 16;" :: "r"(d), "l"(s) : "memory")
#define CPCOMMIT() asm volatile("cp.async.commit_group;" ::: "memory")
#define CPWAIT(n)  asm volatile("cp.async.wait_group %0;" :: "n"(n) : "memory")

// ---------------------------------------------------------------------------
// Kernel 1: L2-normalize + per-token 16-bit fixed-point split into s8 hi/lo.
// ---------------------------------------------------------------------------
__global__ void quant_kernel(const float* __restrict__ q,
                             const float* __restrict__ k) {
    int row = blockIdx.x;
    const float* src;
    int8_t *dh, *dl;
    float* dsc;
    int srow;
    if (row < BATCH * SEQ) {
        src = q + (size_t)row * HID;
        dh = g_qh8 + (size_t)row * HID; dl = g_ql8 + (size_t)row * HID;
        dsc = g_qs; srow = row;
    } else {
        int r = row - BATCH * SEQ;
        src = k + (size_t)r * HID;
        dh = g_kh8 + (size_t)r * HID; dl = g_kl8 + (size_t)r * HID;
        dsc = g_ks; srow = r;
    }
    int t = threadIdx.x;
    float v0 = src[t], v1 = src[t + 256], v2 = src[t + 512];
    float ss = v0 * v0 + v1 * v1 + v2 * v2;
#pragma unroll
    for (int o = 16; o > 0; o >>= 1) ss += __shfl_xor_sync(0xFFFFFFFFu, ss, o);
    __shared__ float sred[8];
    __shared__ float s_inv, s_rstep, s_step;
    if ((t & 31) == 0) sred[t >> 5] = ss;
    __syncthreads();
    if (t == 0) {
        float tot = 0.f;
#pragma unroll
        for (int w = 0; w < 8; w++) tot += sred[w];
        s_inv = 1.0f / fmaxf(sqrtf(tot), 1e-12f);
    }
    __syncthreads();
    float inv = s_inv;
    float n0 = v0 * inv, n1 = v1 * inv, n2 = v2 * inv;
    float am = fmaxf(fabsf(n0), fmaxf(fabsf(n1), fabsf(n2)));
#pragma unroll
    for (int o = 16; o > 0; o >>= 1) am = fmaxf(am, __shfl_xor_sync(0xFFFFFFFFu, am, o));
    if ((t & 31) == 0) sred[t >> 5] = am;
    __syncthreads();
    if (t == 0) {
        float mx = 1e-12f;
#pragma unroll
        for (int w = 0; w < 8; w++) mx = fmaxf(mx, sred[w]);
        s_rstep = 32512.0f / mx;
        s_step  = mx / 32512.0f;
        dsc[srow] = s_step;
    }
    __syncthreads();
    float rstep = s_rstep;
#pragma unroll
    for (int e = 0; e < 3; e++) {
        float v = (e == 0 ? n0 : (e == 1 ? n1 : n2));
        int q15 = __float2int_rn(v * rstep);
        int qh = (q15 + 128) >> 8;           // nearest, qh in [-127,127]
        int ql = q15 - (qh << 8);            // in [-128,127]
        dh[t + e * 256] = (int8_t)qh;
        dl[t + e * 256] = (int8_t)ql;
    }
}

// ---------------------------------------------------------------------------
// Kernel 2: tiny tables
// ---------------------------------------------------------------------------
__global__ void tables_kernel(const float* __restrict__ qmask,
                              const float* __restrict__ alpha_raw,
                              const float* __restrict__ logit_scale) {
    int t = threadIdx.x;
    float a = *alpha_raw;
    float alpha = (a > 20.f) ? a : log1pf(expf(a));
    float scale = expf(*logit_scale);
    g_wd[t] = scale * expf(-alpha * (float)t);
    if (t < BATCH) {
        float s = 0.f;
        for (int x = 0; x < SEQ; x++) s += qmask[t * SEQ + x];
        g_invden[t] = 1.0f / fmaxf(s, 1.0f);
    }
}

// ---------------------------------------------------------------------------
// Kernel 3: per-(pair, s-half) int8x4 IMMA GEMM 128x256xK768 (two 128-t
// halves, online softmax merge), fused decay + masked softmax epilogue.
// ---------------------------------------------------------------------------
__global__ __launch_bounds__(NTP, 1)
void pair_kernel(const float* __restrict__ qmask,
                 const float* __restrict__ kmask) {
    extern __shared__ char smem[];
    const uint32_t sb = smem_u32(smem);
    float* s_wd  = (float*)(smem + SM_WD);
    float* s_kv  = (float*)(smem + SM_KV);
    float* s_ks  = (float*)(smem + SM_KS);
    float* s_qs  = (float*)(smem + SM_QS);
    float* s_red = (float*)(smem + SM_RED);
    float* s_hm  = (float*)(smem + SM_HM);
    float* s_hz  = (float*)(smem + SM_HZ);
    float* s_hs  = (float*)(smem + SM_HS);
    float* stg_max = (float*)(smem + SM_SMAX);
    float* stg_z   = (float*)(smem + SM_SZ);
    float* stg_s   = (float*)(smem + SM_SS);

    const int tid = threadIdx.x;
    const int w = tid >> 5, lane = tid & 31;
    const int wr = w >> 2, wc = w & 3;
    const int bx = blockIdx.x;
    const int pair = bx >> 1, shalf = bx & 1;
    const int i = pair >> 5, j = pair & 31;
    const int s0 = shalf * 128;

    const int8_t* a_h = g_qh8 + ((size_t)i * SEQ + s0) * HID;
    const int8_t* a_l = g_ql8 + ((size_t)i * SEQ + s0) * HID;

    if (tid < SEQ) {
        s_wd[tid] = g_wd[tid];
        s_kv[tid] = (kmask[j * SEQ + tid] > 0.f) ? 1.f : 0.f;
        s_ks[tid] = g_ks[j * SEQ + tid];
    }
    if (tid < 128) s_qs[tid] = g_qs[i * SEQ + s0 + tid];

    // issue one K-chunk of cp.async loads (all 4 tiles) into buffer `buf`
    auto issue = [&](int h, int c, int buf) {
        const int kc = c * KC;
        const int8_t* b_h = g_kh8 + ((size_t)j * SEQ + h * 128) * HID;
        const int8_t* b_l = g_kl8 + ((size_t)j * SEQ + h * 128) * HID;
        const uint32_t tb = sb + SM_TILES + buf * BUFSZ;
#pragma unroll
        for (int qq = 0; qq < 2; qq++) {
            int idx = qq * NTP + tid;
            int row = idx >> 3, g = idx & 7;
            uint32_t doff = row * ROWB + g * 16;
            size_t soff = (size_t)row * HID + kc + g * 16;
            CP16(tb + OFF_AH + doff, a_h + soff);
            CP16(tb + OFF_AL + doff, a_l + soff);
            CP16(tb + OFF_BH + doff, b_h + soff);
            CP16(tb + OFF_BL + doff, b_l + soff);
        }
        CPCOMMIT();
    };

    const int lr = lane & 7, ls = lane >> 3;

    int acc1[2][4][4], acc23[2][4][4], acc4[2][4][4];

    issue(0, 0, 0);

    for (int h = 0; h < 2; h++) {
#pragma unroll
        for (int mi = 0; mi < 2; mi++)
#pragma unroll
            for (int ni = 0; ni < 4; ni++)
#pragma unroll
                for (int e = 0; e < 4; e++) {
                    acc1[mi][ni][e] = 0; acc23[mi][ni][e] = 0; acc4[mi][ni][e] = 0;
                }

        for (int c = 0; c < NCH; c++) {
            if (c < NCH - 1)       issue(h, c + 1, (c + 1) & 1);
            else if (h == 0)       issue(1, 0, 0);
            if (c < NCH - 1 || h == 0) { CPWAIT(1); } else { CPWAIT(0); }
            __syncthreads();

            const uint32_t tb = sb + SM_TILES + (c & 1) * BUFSZ;
#pragma unroll
            for (int g = 0; g < 4; g++) {
                uint32_t qh[2][4], ql[2][4], kh[2][4], kl[2][4];
#pragma unroll
                for (int mi = 0; mi < 2; mi++) {
                    uint32_t aa = tb + OFF_AH +
                        (uint32_t)(wr * 32 + mi * 16 + lr + (ls & 1) * 8) * ROWB +
                        g * 32 + (ls >> 1) * 16;
                    LDSM4(qh[mi], aa);
                    LDSM4(ql[mi], aa + (OFF_AL - OFF_AH));
                }
#pragma unroll
                for (int nh = 0; nh < 2; nh++) {
                    uint32_t ba = tb + OFF_BH +
                        (uint32_t)(wc * 32 + nh * 16 + lr + (ls >> 1) * 8) * ROWB +
                        g * 32 + (ls & 1) * 16;
                    LDSM4(kh[nh], ba);
                    LDSM4(kl[nh], ba + (OFF_BL - OFF_BH));
                }
#pragma unroll
                for (int mi = 0; mi < 2; mi++)
#pragma unroll
                    for (int nh = 0; nh < 2; nh++)
#pragma unroll
                        for (int sub = 0; sub < 2; sub++) {
                            int ni = nh * 2 + sub;
                            uint32_t bh0 = kh[nh][sub * 2], bh1 = kh[nh][sub * 2 + 1];
                            uint32_t bl0 = kl[nh][sub * 2], bl1 = kl[nh][sub * 2 + 1];
                            IMMA(acc1[mi][ni],  qh[mi], bh0, bh1);
                            IMMA(acc23[mi][ni], qh[mi], bl0, bl1);
                            IMMA(acc23[mi][ni], ql[mi], bh0, bh1);
                            IMMA(acc4[mi][ni],  ql[mi], bl0, bl1);
                        }
            }
            __syncthreads();
        }

        // ---- epilogue for this t-half ------------------------------------
        float simv[4][8];
#pragma unroll
        for (int mi = 0; mi < 2; mi++)
#pragma unroll
            for (int rh = 0; rh < 2; rh++) {
                int mr = mi * 2 + rh;
                int row = wr * 32 + mi * 16 + rh * 8 + (lane >> 2);
                float qs = s_qs[row];
                int sg = s0 + row;
                float m = NEG_HUGE;
#pragma unroll
                for (int ni = 0; ni < 4; ni++)
#pragma unroll
                    for (int ee = 0; ee < 2; ee++) {
                        int tg = h * 128 + wc * 32 + ni * 8 + 2 * (lane & 3) + ee;
                        int ai = rh * 2 + ee;
                        float I = fmaf(65536.f, (float)acc1[mi][ni][ai],
                                  fmaf(256.f, (float)acc23[mi][ni][ai],
                                       (float)acc4[mi][ni][ai]));
                        float sim = qs * s_ks[tg] * I;
                        simv[mr][ni * 2 + ee] = sim;
                        int d = sg - tg; d = (d < 0) ? -d : d;
                        float l = sim * s_wd[d];
                        if (s_kv[tg] > 0.f) m = fmaxf(m, l);
                    }
                m = fmaxf(m, __shfl_xor_sync(0xFFFFFFFFu, m, 1));
                m = fmaxf(m, __shfl_xor_sync(0xFFFFFFFFu, m, 2));
                if ((lane & 3) == 0) stg_max[row * 4 + wc] = m;
            }
        __syncthreads();
#pragma unroll
        for (int mi = 0; mi < 2; mi++)
#pragma unroll
            for (int rh = 0; rh < 2; rh++) {
                int mr = mi * 2 + rh;
                int row = wr * 32 + mi * 16 + rh * 8 + (lane >> 2);
                int sg = s0 + row;
                float M = fmaxf(fmaxf(stg_max[row * 4], stg_max[row * 4 + 1]),
                                fmaxf(stg_max[row * 4 + 2], stg_max[row * 4 + 3]));
                float Z = 0.f, S = 0.f;
#pragma unroll
                for (int ni = 0; ni < 4; ni++)
#pragma unroll
                    for (int ee = 0; ee < 2; ee++) {
                        int tg = h * 128 + wc * 32 + ni * 8 + 2 * (lane & 3) + ee;
                        float sim = simv[mr][ni * 2 + ee];
                        int d = sg - tg; d = (d < 0) ? -d : d;
                        float l = sim * s_wd[d];
                        float ex = (s_kv[tg] > 0.f && M > NEG_HUGE) ? __expf(l - M) : 0.f;
                        Z += ex; S += ex * sim;
                    }
                Z += __shfl_xor_sync(0xFFFFFFFFu, Z, 1);
                Z += __shfl_xor_sync(0xFFFFFFFFu, Z, 2);
                S += __shfl_xor_sync(0xFFFFFFFFu, S, 1);
                S += __shfl_xor_sync(0xFFFFFFFFu, S, 2);
                if ((lane & 3) == 0) { stg_z[row * 4 + wc] = Z; stg_s[row * 4 + wc] = S; }
            }
        __syncthreads();
        if (tid < 128) {
            int row = tid;
            float M = fmaxf(fmaxf(stg_max[row * 4], stg_max[row * 4 + 1]),
                            fmaxf(stg_max[row * 4 + 2], stg_max[row * 4 + 3]));
            float Z = stg_z[row * 4] + stg_z[row * 4 + 1] + stg_z[row * 4 + 2] + stg_z[row * 4 + 3];
            float S = stg_s[row * 4] + stg_s[row * 4 + 1] + stg_s[row * 4 + 2] + stg_s[row * 4 + 3];
            if (h == 0) {
                s_hm[row] = M; s_hz[row] = Z; s_hs[row] = S;
            } else {
                float M0 = s_hm[row], Z0 = s_hz[row], S0 = s_hs[row];
                float Mf = fmaxf(M0, M);
                float Zf = 0.f, Sf = 0.f;
                if (M0 > NEG_HUGE) { float f0 = __expf(M0 - Mf); Zf += Z0 * f0; Sf += S0 * f0; }
                if (M  > NEG_HUGE) { float f1 = __expf(M - Mf);  Zf += Z * f1;  Sf += S * f1; }
                float sc = (Zf > 0.f) ? (Sf / Zf) : 0.f;
                float val = sc * qmask[i * SEQ + s0 + row];
#pragma unroll
                for (int o = 16; o > 0; o >>= 1) val += __shfl_xor_sync(0xFFFFFFFFu, val, o);
                if (lane == 0) s_red[w] = val;
            }
        }
        __syncthreads();
    }

    if (tid == 0) {
        float tot = s_red[0] + s_red[1] + s_red[2] + s_red[3];
        g_partial[bx] = tot;
    }
}

// ---------------------------------------------------------------------------
// Kernel 4: combine halves, apply 1/denom
// ---------------------------------------------------------------------------
__global__ void finalize_kernel(float* __restrict__ out) {
    int p = blockIdx.x * blockDim.x + threadIdx.x;
    if (p < BATCH * BATCH)
        out[p] = (g_partial[2 * p] + g_partial[2 * p + 1]) * g_invden[p >> 5];
}

// ---------------------------------------------------------------------------
extern "C" void kernel_launch(void* const* d_in, const int* in_sizes, int n_in,
                              void* d_out, int out_size) {
    const float* q  = (const float*)d_in[0];
    const float* k  = (const float*)d_in[1];
    const float* qm = (const float*)d_in[2];
    const float* km = (const float*)d_in[3];
    const float* ar = (const float*)d_in[4];
    const float* ls = (const float*)d_in[5];
    float* out = (float*)d_out;

    static int attr_done = 0;
    if (!attr_done) {
        cudaFuncSetAttribute(pair_kernel, cudaFuncAttributeMaxDynamicSharedMemorySize, SMEM_TOTAL);
        attr_done = 1;
    }

    quant_kernel<<<2 * BATCH * SEQ, 256>>>(q, k);
    tables_kernel<<<1, 256>>>(qm, ar, ls);
    pair_kernel<<<BATCH * BATCH * 2, NTP, SMEM_TOTAL>>>(qm, km);
    finalize_kernel<<<4, 256>>>(out);
}

// round 8
// speedup vs baseline: 5.9214x; 5.9214x over previous
#include <cuda_runtime.h>
#include <cuda_fp16.h>
#include <math.h>
#include <cstdint>

#define BATCH 32
#define SEQ   256
#define HID   768

#define NTP 512                 // 16 warps = 4 (m-rows) x 4 (n-cols)
#define KC  32                  // fp16 elems per K chunk (64B rows)
#define NCH (HID / KC)          // 24 chunks per product
#define NCC (2 * NCH)           // 48 total chunk-iterations (hh then hl)
#define ROWB 80                 // 64B data + 16B pad (16B-aligned for cp.async)

// smem layout (dynamic)
#define SM_WD    0
#define SM_KV    1024
#define SM_RED   2048
#define SM_SMAX  2112           // [128][4]
#define SM_SZ    4160
#define SM_SS    6208
#define SM_TILES 8448
#define OFF_A    0              // 128 rows * 80B = 10240
#define OFF_B    10240          // 256 rows * 80B = 20480
#define BUFSZ    30720
#define SMEM_TOTAL (SM_TILES + 2 * BUFSZ)   // 69888

#define NEG_HUGE (-3.402823466e38f)

// Scratch (allocation-free rule: __device__ globals)
__device__ __half g_qh[BATCH * SEQ * HID];   // fp16(q_norm)
__device__ __half g_kh[BATCH * SEQ * HID];   // fp16(k_norm)
__device__ __half g_kl[BATCH * SEQ * HID];   // fp16(k_norm - fp16(k_norm))
__device__ float  g_wd[SEQ];
__device__ float  g_invden[BATCH];
__device__ float  g_partial[BATCH * BATCH * 2];

__device__ __forceinline__ uint32_t smem_u32(const void* p) {
    uint32_t a;
    asm("{ .reg .u64 t; cvta.to.shared.u64 t, %1; cvt.u32.u64 %0, t; }" : "=r"(a) : "l"(p));
    return a;
}

#define LDSM4(A, addr)                                                          \
    asm volatile("ldmatrix.sync.aligned.m8n8.x4.shared.b16 {%0,%1,%2,%3}, [%4];"\
        : "=r"((A)[0]), "=r"((A)[1]), "=r"((A)[2]), "=r"((A)[3]) : "r"(addr))

#define MMAH(acc, A, b0, b1)                                                    \
    asm volatile("mma.sync.aligned.m16n8k16.row.col.f32.f16.f16.f32 "           \
        "{%0,%1,%2,%3}, {%4,%5,%6,%7}, {%8,%9}, {%0,%1,%2,%3};"                 \
        : "+f"((acc)[0]), "+f"((acc)[1]), "+f"((acc)[2]), "+f"((acc)[3])        \
        : "r"((A)[0]), "r"((A)[1]), "r"((A)[2]), "r"((A)[3]), "r"(b0), "r"(b1))

#define CP16(d, s) \
    asm volatile("cp.async.cg.shared.global [%0], [%1], 16;" :: "r"(d), "l"(s) : "memory")
#define CPCOMMIT() asm volatile("cp.async.commit_group;" ::: "memory")
#define CPWAIT(n)  asm volatile("cp.async.wait_group %0;" :: "n"(n) : "memory")

// ---------------------------------------------------------------------------
// Kernel 1: L2-normalize; q -> fp16; k -> fp16 hi + fp16 residual.
// ---------------------------------------------------------------------------
__global__ void quant_kernel(const float* __restrict__ q,
                             const float* __restrict__ k) {
    int row = blockIdx.x;
    const bool is_q = (row < BATCH * SEQ);
    int r = is_q ? row : row - BATCH * SEQ;
    const float* src = (is_q ? q : k) + (size_t)r * HID;
    int t = threadIdx.x;
    float v0 = src[t], v1 = src[t + 256], v2 = src[t + 512];
    float ss = v0 * v0 + v1 * v1 + v2 * v2;
#pragma unroll
    for (int o = 16; o > 0; o >>= 1) ss += __shfl_xor_sync(0xFFFFFFFFu, ss, o);
    __shared__ float sred[8];
    __shared__ float s_inv;
    if ((t & 31) == 0) sred[t >> 5] = ss;
    __syncthreads();
    if (t == 0) {
        float tot = 0.f;
#pragma unroll
        for (int w = 0; w < 8; w++) tot += sred[w];
        s_inv = 1.0f / fmaxf(sqrtf(tot), 1e-12f);
    }
    __syncthreads();
    float inv = s_inv;
    if (is_q) {
        __half* dh = g_qh + (size_t)r * HID;
#pragma unroll
        for (int e = 0; e < 3; e++) {
            float v = (e == 0 ? v0 : (e == 1 ? v1 : v2)) * inv;
            dh[t + e * 256] = __float2half(v);
        }
    } else {
        __half* dh = g_kh + (size_t)r * HID;
        __half* dl = g_kl + (size_t)r * HID;
#pragma unroll
        for (int e = 0; e < 3; e++) {
            float v = (e == 0 ? v0 : (e == 1 ? v1 : v2)) * inv;
            __half h = __float2half(v);
            dh[t + e * 256] = h;
            dl[t + e * 256] = __float2half(v - __half2float(h));
        }
    }
}

// ---------------------------------------------------------------------------
// Kernel 2: tiny tables
// ---------------------------------------------------------------------------
__global__ void tables_kernel(const float* __restrict__ qmask,
                              const float* __restrict__ alpha_raw,
                              const float* __restrict__ logit_scale) {
    int t = threadIdx.x;
    float a = *alpha_raw;
    float alpha = (a > 20.f) ? a : log1pf(expf(a));
    float scale = expf(*logit_scale);
    g_wd[t] = scale * expf(-alpha * (float)t);
    if (t < BATCH) {
        float s = 0.f;
        for (int x = 0; x < SEQ; x++) s += qmask[t * SEQ + x];
        g_invden[t] = 1.0f / fmaxf(s, 1.0f);
    }
}

// ---------------------------------------------------------------------------
// Kernel 3: per-(pair, s-half) fp16 2-product MMA GEMM:
// sim = fp16(q) . (fp16(k) + resid(k)) accumulated into one fp32 acc.
// 128(s) x 256(t) block tile, warp tile 32x64, cp.async double buffer.
// ---------------------------------------------------------------------------
__global__ __launch_bounds__(NTP, 1)
void pair_kernel(const float* __restrict__ qmask,
                 const float* __restrict__ kmask) {
    extern __shared__ char smem[];
    const uint32_t sb = smem_u32(smem);
    float* s_wd  = (float*)(smem + SM_WD);
    float* s_kv  = (float*)(smem + SM_KV);
    float* s_red = (float*)(smem + SM_RED);
    float* stg_max = (float*)(smem + SM_SMAX);
    float* stg_z   = (float*)(smem + SM_SZ);
    float* stg_s   = (float*)(smem + SM_SS);

    const int tid = threadIdx.x;
    const int w = tid >> 5, lane = tid & 31;
    const int wr = w >> 2, wc = w & 3;
    const int bx = blockIdx.x;
    const int pair = bx >> 1, shalf = bx & 1;
    const int i = pair >> 5, j = pair & 31;
    const int s0 = shalf * 128;

    const __half* Ag  = g_qh + ((size_t)i * SEQ + s0) * HID;
    const __half* Bh_g = g_kh + (size_t)j * SEQ * HID;
    const __half* Bl_g = g_kl + (size_t)j * SEQ * HID;

    if (tid < SEQ) {
        s_wd[tid] = g_wd[tid];
        s_kv[tid] = (kmask[j * SEQ + tid] > 0.f) ? 1.f : 0.f;
    }

    float acc[2][8][4];
#pragma unroll
    for (int mi = 0; mi < 2; mi++)
#pragma unroll
        for (int ni = 0; ni < 8; ni++)
#pragma unroll
            for (int e = 0; e < 4; e++) acc[mi][ni][e] = 0.f;

    // cp.async one chunk (A 8KB + B 16KB) into buffer `buf`
    auto issue = [&](int cc, int buf) {
        const int kcol = (cc % NCH) * KC;
        const __half* Bg = (cc < NCH) ? Bh_g : Bl_g;
        const uint32_t tb = sb + SM_TILES + buf * BUFSZ;
        {   // A: 128 rows x 64B = 512 x 16B, 1 per thread
            int row = tid >> 2, g = tid & 3;
            CP16(tb + OFF_A + row * ROWB + g * 16,
                 Ag + (size_t)row * HID + kcol + g * 8);
        }
#pragma unroll
        for (int qq = 0; qq < 2; qq++) {  // B: 256 rows x 64B = 1024 x 16B
            int idx = qq * NTP + tid;
            int row = idx >> 2, g = idx & 3;
            CP16(tb + OFF_B + row * ROWB + g * 16,
                 Bg + (size_t)row * HID + kcol + g * 8);
        }
        CPCOMMIT();
    };

    issue(0, 0);

    const uint32_t lrow = lane & 15, lk16 = (lane >> 4) * 16;
    const uint32_t bln = (lane >> 2), blc = (lane & 3) * 4;

    for (int cc = 0; cc < NCC; cc++) {
        if (cc + 1 < NCC) { issue(cc + 1, (cc + 1) & 1); CPWAIT(1); }
        else             { CPWAIT(0); }
        __syncthreads();

        const uint32_t tb = sb + SM_TILES + (cc & 1) * BUFSZ;
#pragma unroll
        for (int k16 = 0; k16 < 2; k16++) {
            uint32_t af[2][4];
            uint32_t koff = k16 * 32 + lk16;
#pragma unroll
            for (int mi = 0; mi < 2; mi++) {
                uint32_t row = wr * 32 + mi * 16 + lrow;
                LDSM4(af[mi], tb + OFF_A + row * ROWB + koff);
            }
#pragma unroll
            for (int ni = 0; ni < 8; ni++) {
                uint32_t n = wc * 64 + ni * 8 + bln;
                uint32_t ba = tb + OFF_B + n * ROWB + k16 * 32 + blc;
                uint32_t b0 = *(const uint32_t*)__cvta_shared_to_generic(ba);
                uint32_t b1 = *(const uint32_t*)__cvta_shared_to_generic(ba + 16);
                MMAH(acc[0][ni], af[0], b0, b1);
                MMAH(acc[1][ni], af[1], b0, b1);
            }
        }
        __syncthreads();   // all warps done with this buffer before it is re-filled
    }

    // ---- epilogue: decay + masked softmax over t, score = sum p*sim ------
    // stage 1: per-row max over this warp's 64 cols
#pragma unroll
    for (int mi = 0; mi < 2; mi++)
#pragma unroll
        for (int q8 = 0; q8 < 2; q8++) {
            int r = wr * 32 + mi * 16 + q8 * 8 + (lane >> 2);
            int sg = s0 + r;
            float m = NEG_HUGE;
#pragma unroll
            for (int ni = 0; ni < 8; ni++)
#pragma unroll
                for (int e = 0; e < 2; e++) {
                    int t = wc * 64 + ni * 8 + 2 * (lane & 3) + e;
                    float v = acc[mi][ni][q8 * 2 + e];
                    int d = sg - t; d = (d < 0) ? -d : d;
                    float l = v * s_wd[d];
                    if (s_kv[t] > 0.f) m = fmaxf(m, l);
                }
            m = fmaxf(m, __shfl_xor_sync(0xFFFFFFFFu, m, 1));
            m = fmaxf(m, __shfl_xor_sync(0xFFFFFFFFu, m, 2));
            if ((lane & 3) == 0) stg_max[r * 4 + wc] = m;
        }
    __syncthreads();

    // stage 2: exp-sum and weighted sim-sum with block-wide row max
#pragma unroll
    for (int mi = 0; mi < 2; mi++)
#pragma unroll
        for (int q8 = 0; q8 < 2; q8++) {
            int r = wr * 32 + mi * 16 + q8 * 8 + (lane >> 2);
            int sg = s0 + r;
            float M = fmaxf(fmaxf(stg_max[r * 4], stg_max[r * 4 + 1]),
                            fmaxf(stg_max[r * 4 + 2], stg_max[r * 4 + 3]));
            float Z = 0.f, S = 0.f;
#pragma unroll
            for (int ni = 0; ni < 8; ni++)
#pragma unroll
                for (int e = 0; e < 2; e++) {
                    int t = wc * 64 + ni * 8 + 2 * (lane & 3) + e;
                    float v = acc[mi][ni][q8 * 2 + e];
                    int d = sg - t; d = (d < 0) ? -d : d;
                    float l = v * s_wd[d];
                    float ex = (s_kv[t] > 0.f && M > NEG_HUGE) ? __expf(l - M) : 0.f;
                    Z += ex; S += ex * v;
                }
            Z += __shfl_xor_sync(0xFFFFFFFFu, Z, 1);
            Z += __shfl_xor_sync(0xFFFFFFFFu, Z, 2);
            S += __shfl_xor_sync(0xFFFFFFFFu, S, 1);
            S += __shfl_xor_sync(0xFFFFFFFFu, S, 2);
            if ((lane & 3) == 0) { stg_z[r * 4 + wc] = Z; stg_s[r * 4 + wc] = S; }
        }
    __syncthreads();

    // stage 3: combine warp-cols, apply q_mask, block-reduce
    float val = 0.f;
    if (tid < 128) {
        int r = tid;
        float Z = stg_z[r * 4] + stg_z[r * 4 + 1] + stg_z[r * 4 + 2] + stg_z[r * 4 + 3];
        float S = stg_s[r * 4] + stg_s[r * 4 + 1] + stg_s[r * 4 + 2] + stg_s[r * 4 + 3];
        float sc = (Z > 0.f) ? (S / Z) : 0.f;
        val = sc * qmask[i * SEQ + s0 + r];
    }
#pragma unroll
    for (int o = 16; o > 0; o >>= 1) val += __shfl_xor_sync(0xFFFFFFFFu, val, o);
    if (tid < 128 && lane == 0) s_red[w] = val;
    __syncthreads();
    if (tid == 0) {
        g_partial[bx] = s_red[0] + s_red[1] + s_red[2] + s_red[3];
    }
}

// ---------------------------------------------------------------------------
// Kernel 4: combine halves, apply 1/denom
// ---------------------------------------------------------------------------
__global__ void finalize_kernel(float* __restrict__ out) {
    int p = blockIdx.x * blockDim.x + threadIdx.x;
    if (p < BATCH * BATCH)
        out[p] = (g_partial[2 * p] + g_partial[2 * p + 1]) * g_invden[p >> 5];
}

// ---------------------------------------------------------------------------
extern "C" void kernel_launch(void* const* d_in, const int* in_sizes, int n_in,
                              void* d_out, int out_size) {
    const float* q  = (const float*)d_in[0];
    const float* k  = (const float*)d_in[1];
    const float* qm = (const float*)d_in[2];
    const float* km = (const float*)d_in[3];
    const float* ar = (const float*)d_in[4];
    const float* ls = (const float*)d_in[5];
    float* out = (float*)d_out;

    static int attr_done = 0;
    if (!attr_done) {
        cudaFuncSetAttribute(pair_kernel, cudaFuncAttributeMaxDynamicSharedMemorySize, SMEM_TOTAL);
        attr_done = 1;
    }

    quant_kernel<<<2 * BATCH * SEQ, 256>>>(q, k);
    tables_kernel<<<1, 256>>>(qm, ar, ls);
    pair_kernel<<<BATCH * BATCH * 2, NTP, SMEM_TOTAL>>>(qm, km);
    finalize_kernel<<<4, 256>>>(out);
}

// round 9
// speedup vs baseline: 10.3172x; 1.7424x over previous
#include <cuda_runtime.h>
#include <cuda_fp16.h>
#include <math.h>
#include <cstdint>

#define BATCH 32
#define SEQ   256
#define HID   768

#define NTP 512                 // 16 warps = 4 (m-rows) x 4 (n-cols)
#define KC  32                  // fp16 elems per K chunk (64B rows)
#define NCH (HID / KC)          // 24 chunks
#define ROWB 80                 // 64B data + 16B pad (16B-aligned for cp.async)

// smem layout (dynamic)
#define SM_WD    0
#define SM_KV    1024
#define SM_RED   2048
#define SM_SMAX  2112           // [128][4]
#define SM_SZ    4160
#define SM_SS    6208
#define SM_TILES 8448
#define OFF_A    0              // 128 rows * 80B = 10240
#define OFF_B    10240          // 256 rows * 80B = 20480
#define BUFSZ    30720
#define SMEM_TOTAL (SM_TILES + 2 * BUFSZ)   // 69888

#define NEG_HUGE (-3.402823466e38f)

// Scratch (allocation-free rule: __device__ globals)
__device__ __half g_qh[BATCH * SEQ * HID];   // fp16(q_norm)
__device__ __half g_kh[BATCH * SEQ * HID];   // fp16(k_norm)
__device__ float  g_wd[SEQ];
__device__ float  g_invden[BATCH];
__device__ float  g_partial[BATCH * BATCH * 2];

__device__ __forceinline__ uint32_t smem_u32(const void* p) {
    uint32_t a;
    asm("{ .reg .u64 t; cvta.to.shared.u64 t, %1; cvt.u32.u64 %0, t; }" : "=r"(a) : "l"(p));
    return a;
}

#define LDSM4(A, addr)                                                          \
    asm volatile("ldmatrix.sync.aligned.m8n8.x4.shared.b16 {%0,%1,%2,%3}, [%4];"\
        : "=r"((A)[0]), "=r"((A)[1]), "=r"((A)[2]), "=r"((A)[3]) : "r"(addr))

#define LDSB32(r, addr) \
    asm volatile("ld.shared.b32 %0, [%1];" : "=r"(r) : "r"(addr))

#define MMAH(acc, A, b0, b1)                                                    \
    asm volatile("mma.sync.aligned.m16n8k16.row.col.f32.f16.f16.f32 "           \
        "{%0,%1,%2,%3}, {%4,%5,%6,%7}, {%8,%9}, {%0,%1,%2,%3};"                 \
        : "+f"((acc)[0]), "+f"((acc)[1]), "+f"((acc)[2]), "+f"((acc)[3])        \
        : "r"((A)[0]), "r"((A)[1]), "r"((A)[2]), "r"((A)[3]), "r"(b0), "r"(b1))

#define CP16(d, s) \
    asm volatile("cp.async.cg.shared.global [%0], [%1], 16;" :: "r"(d), "l"(s) : "memory")
#define CPCOMMIT() asm volatile("cp.async.commit_group;" ::: "memory")
#define CPWAIT(n)  asm volatile("cp.async.wait_group %0;" :: "n"(n) : "memory")

// ---------------------------------------------------------------------------
// Kernel 1: L2-normalize; q,k -> fp16.
// ---------------------------------------------------------------------------
__global__ void quant_kernel(const float* __restrict__ q,
                             const float* __restrict__ k) {
    int row = blockIdx.x;
    const bool is_q = (row < BATCH * SEQ);
    int r = is_q ? row : row - BATCH * SEQ;
    const float* src = (is_q ? q : k) + (size_t)r * HID;
    __half* dh = (is_q ? g_qh : g_kh) + (size_t)r * HID;
    int t = threadIdx.x;
    float v0 = src[t], v1 = src[t + 256], v2 = src[t + 512];
    float ss = v0 * v0 + v1 * v1 + v2 * v2;
#pragma unroll
    for (int o = 16; o > 0; o >>= 1) ss += __shfl_xor_sync(0xFFFFFFFFu, ss, o);
    __shared__ float sred[8];
    __shared__ float s_inv;
    if ((t & 31) == 0) sred[t >> 5] = ss;
    __syncthreads();
    if (t == 0) {
        float tot = 0.f;
#pragma unroll
        for (int w = 0; w < 8; w++) tot += sred[w];
        s_inv = 1.0f / fmaxf(sqrtf(tot), 1e-12f);
    }
    __syncthreads();
    float inv = s_inv;
    dh[t]       = __float2half(v0 * inv);
    dh[t + 256] = __float2half(v1 * inv);
    dh[t + 512] = __float2half(v2 * inv);
}

// ---------------------------------------------------------------------------
// Kernel 2: tiny tables
// ---------------------------------------------------------------------------
__global__ void tables_kernel(const float* __restrict__ qmask,
                              const float* __restrict__ alpha_raw,
                              const float* __restrict__ logit_scale) {
    int t = threadIdx.x;
    float a = *alpha_raw;
    float alpha = (a > 20.f) ? a : log1pf(expf(a));
    float scale = expf(*logit_scale);
    g_wd[t] = scale * expf(-alpha * (float)t);
    if (t < BATCH) {
        float s = 0.f;
        for (int x = 0; x < SEQ; x++) s += qmask[t * SEQ + x];
        g_invden[t] = 1.0f / fmaxf(s, 1.0f);
    }
}

// ---------------------------------------------------------------------------
// Kernel 3: per-(pair, s-half) fp16 single-product MMA GEMM sim = hq . hk,
// 128(s) x 256(t) block tile, warp tile 32x64, cp.async double buffer,
// fused decay + masked softmax epilogue.
// ---------------------------------------------------------------------------
__global__ __launch_bounds__(NTP, 1)
void pair_kernel(const float* __restrict__ qmask,
                 const float* __restrict__ kmask) {
    extern __shared__ char smem[];
    const uint32_t sb = smem_u32(smem);
    float* s_wd  = (float*)(smem + SM_WD);
    float* s_kv  = (float*)(smem + SM_KV);
    float* s_red = (float*)(smem + SM_RED);
    float* stg_max = (float*)(smem + SM_SMAX);
    float* stg_z   = (float*)(smem + SM_SZ);
    float* stg_s   = (float*)(smem + SM_SS);

    const int tid = threadIdx.x;
    const int w = tid >> 5, lane = tid & 31;
    const int wr = w >> 2, wc = w & 3;
    const int bx = blockIdx.x;
    const int pair = bx >> 1, shalf = bx & 1;
    const int i = pair >> 5, j = pair & 31;
    const int s0 = shalf * 128;

    const __half* Ag = g_qh + ((size_t)i * SEQ + s0) * HID;
    const __half* Bg = g_kh + (size_t)j * SEQ * HID;

    if (tid < SEQ) {
        s_wd[tid] = g_wd[tid];
        s_kv[tid] = (kmask[j * SEQ + tid] > 0.f) ? 1.f : 0.f;
    }

    float acc[2][8][4];
#pragma unroll
    for (int mi = 0; mi < 2; mi++)
#pragma unroll
        for (int ni = 0; ni < 8; ni++)
#pragma unroll
            for (int e = 0; e < 4; e++) acc[mi][ni][e] = 0.f;

    // cp.async one chunk (A 8KB + B 16KB) into buffer `buf`
    auto issue = [&](int cc, int buf) {
        const int kcol = cc * KC;
        const uint32_t tb = sb + SM_TILES + buf * BUFSZ;
        {   // A: 128 rows x 64B = 512 x 16B, 1 per thread
            int row = tid >> 2, g = tid & 3;
            CP16(tb + OFF_A + row * ROWB + g * 16,
                 Ag + (size_t)row * HID + kcol + g * 8);
        }
#pragma unroll
        for (int qq = 0; qq < 2; qq++) {  // B: 256 rows x 64B = 1024 x 16B
            int idx = qq * NTP + tid;
            int row = idx >> 2, g = idx & 3;
            CP16(tb + OFF_B + row * ROWB + g * 16,
                 Bg + (size_t)row * HID + kcol + g * 8);
        }
        CPCOMMIT();
    };

    issue(0, 0);

    const uint32_t lrow = lane & 15, lk16 = (lane >> 4) * 16;
    const uint32_t bln = (lane >> 2), blc = (lane & 3) * 4;

    for (int cc = 0; cc < NCH; cc++) {
        if (cc + 1 < NCH) { issue(cc + 1, (cc + 1) & 1); CPWAIT(1); }
        else             { CPWAIT(0); }
        __syncthreads();

        const uint32_t tb = sb + SM_TILES + (cc & 1) * BUFSZ;
#pragma unroll
        for (int k16 = 0; k16 < 2; k16++) {
            uint32_t af[2][4];
            uint32_t koff = k16 * 32 + lk16;
#pragma unroll
            for (int mi = 0; mi < 2; mi++) {
                uint32_t row = wr * 32 + mi * 16 + lrow;
                LDSM4(af[mi], tb + OFF_A + row * ROWB + koff);
            }
#pragma unroll
            for (int ni = 0; ni < 8; ni++) {
                uint32_t n = wc * 64 + ni * 8 + bln;
                uint32_t ba = tb + OFF_B + n * ROWB + k16 * 32 + blc;
                uint32_t b0, b1;
                LDSB32(b0, ba);
                LDSB32(b1, ba + 16);
                MMAH(acc[0][ni], af[0], b0, b1);
                MMAH(acc[1][ni], af[1], b0, b1);
            }
        }
        __syncthreads();   // all warps done with this buffer before refill
    }

    // ---- epilogue: decay + masked softmax over t, score = sum p*sim ------
    // stage 1: per-row max over this warp's 64 cols
#pragma unroll
    for (int mi = 0; mi < 2; mi++)
#pragma unroll
        for (int q8 = 0; q8 < 2; q8++) {
            int r = wr * 32 + mi * 16 + q8 * 8 + (lane >> 2);
            int sg = s0 + r;
            float m = NEG_HUGE;
#pragma unroll
            for (int ni = 0; ni < 8; ni++)
#pragma unroll
                for (int e = 0; e < 2; e++) {
                    int t = wc * 64 + ni * 8 + 2 * (lane & 3) + e;
                    float v = acc[mi][ni][q8 * 2 + e];
                    int d = sg - t; d = (d < 0) ? -d : d;
                    float l = v * s_wd[d];
                    if (s_kv[t] > 0.f) m = fmaxf(m, l);
                }
            m = fmaxf(m, __shfl_xor_sync(0xFFFFFFFFu, m, 1));
            m = fmaxf(m, __shfl_xor_sync(0xFFFFFFFFu, m, 2));
            if ((lane & 3) == 0) stg_max[r * 4 + wc] = m;
        }
    __syncthreads();

    // stage 2: exp-sum and weighted sim-sum with block-wide row max
#pragma unroll
    for (int mi = 0; mi < 2; mi++)
#pragma unroll
        for (int q8 = 0; q8 < 2; q8++) {
            int r = wr * 32 + mi * 16 + q8 * 8 + (lane >> 2);
            int sg = s0 + r;
            float M = fmaxf(fmaxf(stg_max[r * 4], stg_max[r * 4 + 1]),
                            fmaxf(stg_max[r * 4 + 2], stg_max[r * 4 + 3]));
            float Z = 0.f, S = 0.f;
#pragma unroll
            for (int ni = 0; ni < 8; ni++)
#pragma unroll
                for (int e = 0; e < 2; e++) {
                    int t = wc * 64 + ni * 8 + 2 * (lane & 3) + e;
                    float v = acc[mi][ni][q8 * 2 + e];
                    int d = sg - t; d = (d < 0) ? -d : d;
                    float l = v * s_wd[d];
                    float ex = (s_kv[t] > 0.f && M > NEG_HUGE) ? __expf(l - M) : 0.f;
                    Z += ex; S += ex * v;
                }
            Z += __shfl_xor_sync(0xFFFFFFFFu, Z, 1);
            Z += __shfl_xor_sync(0xFFFFFFFFu, Z, 2);
            S += __shfl_xor_sync(0xFFFFFFFFu, S, 1);
            S += __shfl_xor_sync(0xFFFFFFFFu, S, 2);
            if ((lane & 3) == 0) { stg_z[r * 4 + wc] = Z; stg_s[r * 4 + wc] = S; }
        }
    __syncthreads();

    // stage 3: combine warp-cols, apply q_mask, block-reduce
    float val = 0.f;
    if (tid < 128) {
        int r = tid;
        float Z = stg_z[r * 4] + stg_z[r * 4 + 1] + stg_z[r * 4 + 2] + stg_z[r * 4 + 3];
        float S = stg_s[r * 4] + stg_s[r * 4 + 1] + stg_s[r * 4 + 2] + stg_s[r * 4 + 3];
        float sc = (Z > 0.f) ? (S / Z) : 0.f;
        val = sc * qmask[i * SEQ + s0 + r];
    }
#pragma unroll
    for (int o = 16; o > 0; o >>= 1) val += __shfl_xor_sync(0xFFFFFFFFu, val, o);
    if (tid < 128 && lane == 0) s_red[w] = val;
    __syncthreads();
    if (tid == 0) {
        g_partial[bx] = s_red[0] + s_red[1] + s_red[2] + s_red[3];
    }
}

// ---------------------------------------------------------------------------
// Kernel 4: combine halves, apply 1/denom
// ---------------------------------------------------------------------------
__global__ void finalize_kernel(float* __restrict__ out) {
    int p = blockIdx.x * blockDim.x + threadIdx.x;
    if (p < BATCH * BATCH)
        out[p] = (g_partial[2 * p] + g_partial[2 * p + 1]) * g_invden[p >> 5];
}

// ---------------------------------------------------------------------------
extern "C" void kernel_launch(void* const* d_in, const int* in_sizes, int n_in,
                              void* d_out, int out_size) {
    const float* q  = (const float*)d_in[0];
    const float* k  = (const float*)d_in[1];
    const float* qm = (const float*)d_in[2];
    const float* km = (const float*)d_in[3];
    const float* ar = (const float*)d_in[4];
    const float* ls = (const float*)d_in[5];
    float* out = (float*)d_out;

    static int attr_done = 0;
    if (!attr_done) {
        cudaFuncSetAttribute(pair_kernel, cudaFuncAttributeMaxDynamicSharedMemorySize, SMEM_TOTAL);
        attr_done = 1;
    }

    quant_kernel<<<2 * BATCH * SEQ, 256>>>(q, k);
    tables_kernel<<<1, 256>>>(qm, ar, ls);
    pair_kernel<<<BATCH * BATCH * 2, NTP, SMEM_TOTAL>>>(qm, km);
    finalize_kernel<<<4, 256>>>(out);
}

// round 10
// speedup vs baseline: 12.2344x; 1.1858x over previous
#include <cuda_runtime.h>
#include <cuda_fp16.h>
#include <math.h>
#include <cstdint>

#define BATCH 32
#define SEQ   256
#define HID   768

#define NTP 512                 // 16 warps = 4 (m-rows) x 4 (n-cols)
#define KC  64                  // fp16 elems per K chunk (128B rows)
#define NCH (HID / KC)          // 12 chunks
#define NSTG 3                  // pipeline stages
#define ROWB 144                // 128B data + 16B pad

// smem layout (dynamic)
#define SM_WD    0
#define SM_KV    1024
#define SM_RED   2048
#define SM_SMAX  2112           // [128][4]
#define SM_SZ    4160
#define SM_SS    6208
#define SM_TILES 8448
#define OFF_A    0              // 128 rows * 144B = 18432
#define OFF_B    18432          // 256 rows * 144B = 36864
#define BUFSZ    55296
#define SMEM_TOTAL (SM_TILES + NSTG * BUFSZ)   // 174336

#define NEG_HUGE (-3.402823466e38f)

// Scratch (allocation-free rule: __device__ globals)
__device__ __half g_qh[BATCH * SEQ * HID];   // fp16(q_norm)
__device__ __half g_kh[BATCH * SEQ * HID];   // fp16(k_norm)
__device__ float  g_wd[SEQ];
__device__ float  g_invden[BATCH];
__device__ float  g_partial[BATCH * BATCH * 2];

__device__ __forceinline__ uint32_t smem_u32(const void* p) {
    uint32_t a;
    asm("{ .reg .u64 t; cvta.to.shared.u64 t, %1; cvt.u32.u64 %0, t; }" : "=r"(a) : "l"(p));
    return a;
}

#define LDSM4(A, addr)                                                          \
    asm volatile("ldmatrix.sync.aligned.m8n8.x4.shared.b16 {%0,%1,%2,%3}, [%4];"\
        : "=r"((A)[0]), "=r"((A)[1]), "=r"((A)[2]), "=r"((A)[3]) : "r"(addr))

#define LDSB32(r, addr) \
    asm volatile("ld.shared.b32 %0, [%1];" : "=r"(r) : "r"(addr))

#define MMAH(acc, A, b0, b1)                                                    \
    asm volatile("mma.sync.aligned.m16n8k16.row.col.f32.f16.f16.f32 "           \
        "{%0,%1,%2,%3}, {%4,%5,%6,%7}, {%8,%9}, {%0,%1,%2,%3};"                 \
        : "+f"((acc)[0]), "+f"((acc)[1]), "+f"((acc)[2]), "+f"((acc)[3])        \
        : "r"((A)[0]), "r"((A)[1]), "r"((A)[2]), "r"((A)[3]), "r"(b0), "r"(b1))

#define CP16(d, s) \
    asm volatile("cp.async.cg.shared.global [%0], [%1], 16;" :: "r"(d), "l"(s) : "memory")
#define CPCOMMIT() asm volatile("cp.async.commit_group;" ::: "memory")
#define CPWAIT(n)  asm volatile("cp.async.wait_group %0;" :: "n"(n) : "memory")

// ---------------------------------------------------------------------------
// Kernel 1: L2-normalize; q,k -> fp16.
// ---------------------------------------------------------------------------
__global__ void quant_kernel(const float* __restrict__ q,
                             const float* __restrict__ k) {
    int row = blockIdx.x;
    const bool is_q = (row < BATCH * SEQ);
    int r = is_q ? row : row - BATCH * SEQ;
    const float* src = (is_q ? q : k) + (size_t)r * HID;
    __half* dh = (is_q ? g_qh : g_kh) + (size_t)r * HID;
    int t = threadIdx.x;
    float v0 = src[t], v1 = src[t + 256], v2 = src[t + 512];
    float ss = v0 * v0 + v1 * v1 + v2 * v2;
#pragma unroll
    for (int o = 16; o > 0; o >>= 1) ss += __shfl_xor_sync(0xFFFFFFFFu, ss, o);
    __shared__ float sred[8];
    __shared__ float s_inv;
    if ((t & 31) == 0) sred[t >> 5] = ss;
    __syncthreads();
    if (t == 0) {
        float tot = 0.f;
#pragma unroll
        for (int w = 0; w < 8; w++) tot += sred[w];
        s_inv = 1.0f / fmaxf(sqrtf(tot), 1e-12f);
    }
    __syncthreads();
    float inv = s_inv;
    dh[t]       = __float2half(v0 * inv);
    dh[t + 256] = __float2half(v1 * inv);
    dh[t + 512] = __float2half(v2 * inv);
}

// ---------------------------------------------------------------------------
// Kernel 2: tiny tables
// ---------------------------------------------------------------------------
__global__ void tables_kernel(const float* __restrict__ qmask,
                              const float* __restrict__ alpha_raw,
                              const float* __restrict__ logit_scale) {
    int t = threadIdx.x;
    float a = *alpha_raw;
    float alpha = (a > 20.f) ? a : log1pf(expf(a));
    float scale = expf(*logit_scale);
    g_wd[t] = scale * expf(-alpha * (float)t);
    if (t < BATCH) {
        float s = 0.f;
        for (int x = 0; x < SEQ; x++) s += qmask[t * SEQ + x];
        g_invden[t] = 1.0f / fmaxf(s, 1.0f);
    }
}

// ---------------------------------------------------------------------------
// Kernel 3: per-(pair, s-half) fp16 MMA GEMM sim = hq . hk, 128x256 tile,
// warp tile 32x64, 3-stage cp.async ring with one barrier per chunk,
// fused decay + masked softmax epilogue.
// ---------------------------------------------------------------------------
__global__ __launch_bounds__(NTP, 1)
void pair_kernel(const float* __restrict__ qmask,
                 const float* __restrict__ kmask) {
    extern __shared__ char smem[];
    const uint32_t sb = smem_u32(smem);
    float* s_wd  = (float*)(smem + SM_WD);
    float* s_kv  = (float*)(smem + SM_KV);
    float* s_red = (float*)(smem + SM_RED);
    float* stg_max = (float*)(smem + SM_SMAX);
    float* stg_z   = (float*)(smem + SM_SZ);
    float* stg_s   = (float*)(smem + SM_SS);

    const int tid = threadIdx.x;
    const int w = tid >> 5, lane = tid & 31;
    const int wr = w >> 2, wc = w & 3;
    const int bx = blockIdx.x;
    const int pair = bx >> 1, shalf = bx & 1;
    const int i = pair >> 5, j = pair & 31;
    const int s0 = shalf * 128;

    const __half* Ag = g_qh + ((size_t)i * SEQ + s0) * HID;
    const __half* Bg = g_kh + (size_t)j * SEQ * HID;

    if (tid < SEQ) {
        s_wd[tid] = g_wd[tid];
        s_kv[tid] = (kmask[j * SEQ + tid] > 0.f) ? 1.f : 0.f;
    }

    float acc[2][8][4];
#pragma unroll
    for (int mi = 0; mi < 2; mi++)
#pragma unroll
        for (int ni = 0; ni < 8; ni++)
#pragma unroll
            for (int e = 0; e < 4; e++) acc[mi][ni][e] = 0.f;

    // cp.async one chunk (A 16KB + B 32KB) into stage cc%NSTG
    auto issue = [&](int cc) {
        const int kcol = cc * KC;
        const uint32_t tb = sb + SM_TILES + (cc % NSTG) * BUFSZ;
#pragma unroll
        for (int qq = 0; qq < 2; qq++) {   // A: 128 rows x 8 groups = 1024 x 16B
            int idx = qq * NTP + tid;
            int row = idx >> 3, g = idx & 7;
            CP16(tb + OFF_A + row * ROWB + g * 16,
                 Ag + (size_t)row * HID + kcol + g * 8);
        }
#pragma unroll
        for (int qq = 0; qq < 4; qq++) {   // B: 256 rows x 8 groups = 2048 x 16B
            int idx = qq * NTP + tid;
            int row = idx >> 3, g = idx & 7;
            CP16(tb + OFF_B + row * ROWB + g * 16,
                 Bg + (size_t)row * HID + kcol + g * 8);
        }
        CPCOMMIT();
    };

    issue(0);
    issue(1);

    const uint32_t lrow = lane & 15, lk16 = (lane >> 4) * 16;
    const uint32_t bln = (lane >> 2), blc = (lane & 3) * 4;

    for (int cc = 0; cc < NCH; cc++) {
        CPWAIT(1);           // group cc complete (own thread)
        __syncthreads();     // visibility + all warps done with MMA(cc-1)
        if (cc + 2 < NCH) issue(cc + 2);   // overlaps MMA below

        const uint32_t tb = sb + SM_TILES + (cc % NSTG) * BUFSZ;
#pragma unroll
        for (int k16 = 0; k16 < 4; k16++) {
            uint32_t af[2][4];
            uint32_t koff = k16 * 32 + lk16;
#pragma unroll
            for (int mi = 0; mi < 2; mi++) {
                uint32_t row = wr * 32 + mi * 16 + lrow;
                LDSM4(af[mi], tb + OFF_A + row * ROWB + koff);
            }
#pragma unroll
            for (int ni = 0; ni < 8; ni++) {
                uint32_t n = wc * 64 + ni * 8 + bln;
                uint32_t ba = tb + OFF_B + n * ROWB + k16 * 32 + blc;
                uint32_t b0, b1;
                LDSB32(b0, ba);
                LDSB32(b1, ba + 16);
                MMAH(acc[0][ni], af[0], b0, b1);
                MMAH(acc[1][ni], af[1], b0, b1);
            }
        }
    }
    __syncthreads();   // last buffer consumed by all before epilogue smem reuse

    // ---- epilogue: decay + masked softmax over t, score = sum p*sim ------
    // stage 1: per-row max over this warp's 64 cols
#pragma unroll
    for (int mi = 0; mi < 2; mi++)
#pragma unroll
        for (int q8 = 0; q8 < 2; q8++) {
            int r = wr * 32 + mi * 16 + q8 * 8 + (lane >> 2);
            int sg = s0 + r;
            float m = NEG_HUGE;
#pragma unroll
            for (int ni = 0; ni < 8; ni++)
#pragma unroll
                for (int e = 0; e < 2; e++) {
                    int t = wc * 64 + ni * 8 + 2 * (lane & 3) + e;
                    float v = acc[mi][ni][q8 * 2 + e];
                    int d = sg - t; d = (d < 0) ? -d : d;
                    float l = v * s_wd[d];
                    if (s_kv[t] > 0.f) m = fmaxf(m, l);
                }
            m = fmaxf(m, __shfl_xor_sync(0xFFFFFFFFu, m, 1));
            m = fmaxf(m, __shfl_xor_sync(0xFFFFFFFFu, m, 2));
            if ((lane & 3) == 0) stg_max[r * 4 + wc] = m;
        }
    __syncthreads();

    // stage 2: exp-sum and weighted sim-sum with block-wide row max
#pragma unroll
    for (int mi = 0; mi < 2; mi++)
#pragma unroll
        for (int q8 = 0; q8 < 2; q8++) {
            int r = wr * 32 + mi * 16 + q8 * 8 + (lane >> 2);
            int sg = s0 + r;
            float M = fmaxf(fmaxf(stg_max[r * 4], stg_max[r * 4 + 1]),
                            fmaxf(stg_max[r * 4 + 2], stg_max[r * 4 + 3]));
            float Z = 0.f, S = 0.f;
#pragma unroll
            for (int ni = 0; ni < 8; ni++)
#pragma unroll
                for (int e = 0; e < 2; e++) {
                    int t = wc * 64 + ni * 8 + 2 * (lane & 3) + e;
                    float v = acc[mi][ni][q8 * 2 + e];
                    int d = sg - t; d = (d < 0) ? -d : d;
                    float l = v * s_wd[d];
                    float ex = (s_kv[t] > 0.f && M > NEG_HUGE) ? __expf(l - M) : 0.f;
                    Z += ex; S += ex * v;
                }
            Z += __shfl_xor_sync(0xFFFFFFFFu, Z, 1);
            Z += __shfl_xor_sync(0xFFFFFFFFu, Z, 2);
            S += __shfl_xor_sync(0xFFFFFFFFu, S, 1);
            S += __shfl_xor_sync(0xFFFFFFFFu, S, 2);
            if ((lane & 3) == 0) { stg_z[r * 4 + wc] = Z; stg_s[r * 4 + wc] = S; }
        }
    __syncthreads();

    // stage 3: combine warp-cols, apply q_mask, block-reduce
    float val = 0.f;
    if (tid < 128) {
        int r = tid;
        float Z = stg_z[r * 4] + stg_z[r * 4 + 1] + stg_z[r * 4 + 2] + stg_z[r * 4 + 3];
        float S = stg_s[r * 4] + stg_s[r * 4 + 1] + stg_s[r * 4 + 2] + stg_s[r * 4 + 3];
        float sc = (Z > 0.f) ? (S / Z) : 0.f;
        val = sc * qmask[i * SEQ + s0 + r];
    }
#pragma unroll
    for (int o = 16; o > 0; o >>= 1) val += __shfl_xor_sync(0xFFFFFFFFu, val, o);
    if (tid < 128 && lane == 0) s_red[w] = val;
    __syncthreads();
    if (tid == 0) {
        g_partial[bx] = s_red[0] + s_red[1] + s_red[2] + s_red[3];
    }
}

// ---------------------------------------------------------------------------
// Kernel 4: combine halves, apply 1/denom
// ---------------------------------------------------------------------------
__global__ void finalize_kernel(float* __restrict__ out) {
    int p = blockIdx.x * blockDim.x + threadIdx.x;
    if (p < BATCH * BATCH)
        out[p] = (g_partial[2 * p] + g_partial[2 * p + 1]) * g_invden[p >> 5];
}

// ---------------------------------------------------------------------------
extern "C" void kernel_launch(void* const* d_in, const int* in_sizes, int n_in,
                              void* d_out, int out_size) {
    const float* q  = (const float*)d_in[0];
    const float* k  = (const float*)d_in[1];
    const float* qm = (const float*)d_in[2];
    const float* km = (const float*)d_in[3];
    const float* ar = (const float*)d_in[4];
    const float* ls = (const float*)d_in[5];
    float* out = (float*)d_out;

    static int attr_done = 0;
    if (!attr_done) {
        cudaFuncSetAttribute(pair_kernel, cudaFuncAttributeMaxDynamicSharedMemorySize, SMEM_TOTAL);
        attr_done = 1;
    }

    quant_kernel<<<2 * BATCH * SEQ, 256>>>(q, k);
    tables_kernel<<<1, 256>>>(qm, ar, ls);
    pair_kernel<<<BATCH * BATCH * 2, NTP, SMEM_TOTAL>>>(qm, km);
    finalize_kernel<<<4, 256>>>(out);
}